// round 8
// baseline (speedup 1.0000x reference)
#include <cuda_runtime.h>
#include <cstddef>

#define TT 64
#define LL 512
#define BB 512
#define START_TAG 62
#define STOP_TAG  63
#define NBLK (BB / 4)          // 4 sequences per block

// Scratch (allocation-free requirement).
__device__ float g_partials[BB];
__device__ int   g_count;      // zero-init; reset by last block each launch

#define HBAR(id) asm volatile("bar.sync %0, 64;" :: "r"(id) : "memory")

__device__ __forceinline__ void fma2(unsigned long long& acc,
                                     unsigned long long p,
                                     unsigned long long q) {
    asm("fma.rn.f32x2 %0, %1, %2, %0;" : "+l"(acc) : "l"(p), "l"(q));
}
__device__ __forceinline__ void add2(unsigned long long& a, unsigned long long b) {
    asm("add.rn.f32x2 %0, %0, %1;" : "+l"(a) : "l"(b));
}
__device__ __forceinline__ float2 unpack2(unsigned long long v) {
    float2 r;
    asm("mov.b64 {%0, %1}, %2;" : "=f"(r.x), "=f"(r.y) : "l"(v));
    return r;
}
__device__ __forceinline__ unsigned long long pack2(float lo, float hi) {
    unsigned long long v;
    asm("mov.b64 %0, {%1, %2};" : "=l"(v) : "f"(lo), "f"(hi));
    return v;
}

// Two interleaved full 64-dots. 64 floats = 16 ulonglong2 per sequence;
// pair j (tags 2j,2j+1) multiplies P2[j]. a4[k] holds pairs {2k, 2k+1}.
__device__ __forceinline__ void dot64x2(const float* __restrict__ qa,
                                        const float* __restrict__ qb,
                                        const unsigned long long* __restrict__ P2,
                                        float& sa, float& sb) {
    const ulonglong2* a4 = (const ulonglong2*)qa;
    const ulonglong2* b4 = (const ulonglong2*)qb;
    unsigned long long aa0 = 0, aa1 = 0, bb0 = 0, bb1 = 0;
#pragma unroll
    for (int k = 0; k < 16; ++k) {
        ulonglong2 va = a4[k];
        ulonglong2 vb = b4[k];
        fma2(aa0, P2[2 * k],     va.x);
        fma2(aa1, P2[2 * k + 1], va.y);
        fma2(bb0, P2[2 * k],     vb.x);
        fma2(bb1, P2[2 * k + 1], vb.y);
    }
    add2(aa0, aa1);
    add2(bb0, bb1);
    float2 pa = unpack2(aa0);
    float2 pb = unpack2(bb0);
    sa = pa.x + pa.y;
    sb = pb.x + pb.y;
}

// Single full 64-dot (R4-proven body).
__device__ __forceinline__ float dot64(const float* __restrict__ qbuf,
                                       const unsigned long long* __restrict__ P2) {
    const ulonglong2* q4 = (const ulonglong2*)qbuf;
    unsigned long long a0 = 0, a1 = 0, a2 = 0, a3 = 0;
#pragma unroll
    for (int k = 0; k < TT / 8; ++k) {
        ulonglong2 v = q4[2 * k];
        ulonglong2 w = q4[2 * k + 1];
        fma2(a0, P2[4 * k + 0], v.x);
        fma2(a1, P2[4 * k + 1], v.y);
        fma2(a2, P2[4 * k + 2], w.x);
        fma2(a3, P2[4 * k + 3], w.y);
    }
    add2(a0, a1);
    add2(a2, a3);
    add2(a0, a2);
    float2 sp = unpack2(a0);
    return sp.x + sp.y;
}

__global__ void __launch_bounds__(128, 1) crf_fused_kernel(
    const float* __restrict__ inputs,   // (B, L, T)
    const int*   __restrict__ tags,     // (B, L)
    const int*   __restrict__ mask,     // (B, L)
    const float* __restrict__ trans,    // (T, T)
    float*       __restrict__ out)
{
    const int tid = threadIdx.x;
    const int h   = tid >> 6;          // half: 0 or 1
    const int l   = tid & 63;          // tag owned by this thread
    const int bar = 1 + h;             // named barrier per half
    const int sA  = blockIdx.x * 4 + 2 * h;
    const int sB  = sA + 1;

    __shared__ __align__(16) float q_sh[4][2][TT];
    __shared__ float red2[2][TT];
    __shared__ float dsl[2];
    __shared__ int   flagA[2][2];
    __shared__ int   islast;

    // Packed exp(transition) row for destination tag = l (shared by both seqs).
    unsigned long long P2[TT / 2];
#pragma unroll
    for (int j = 0; j < TT / 2; ++j) {
        float p0 = __expf(trans[l * TT + 2 * j]);
        float p1 = __expf(trans[l * TT + 2 * j + 1]);
        P2[j] = pack2(p0, p1);
    }

    // all-ones mask detection for this half's two sequences.
    int m_and = 1;
    for (int t = l; t < LL; t += 64) {
        m_and &= (mask[sA * LL + t] != 0);
        m_and &= (mask[sB * LL + t] != 0);
    }
    flagA[h][(tid >> 5) & 1] = __all_sync(0xffffffffu, m_and);
    HBAR(bar);
    const int all_ones = flagA[h][0] & flagA[h][1];

    const float* epA = inputs + (size_t)sA * LL * TT + l;
    const float* epB = inputs + (size_t)sB * LL * TT + l;

    float aA, aB, CA, CB;

    if (all_ones) {
        // ===== fast path: two interleaved prob-space recursions per thread ====
        q_sh[2 * h + 0][0][l] = (l == START_TAG) ? 1.0f : 0.0f;
        q_sh[2 * h + 1][0][l] = (l == START_TAG) ? 1.0f : 0.0f;

        float ra0 = epA[0 * TT], ra1 = epA[1 * TT], ra2 = epA[2 * TT], ra3 = epA[3 * TT];
        float rb0 = epB[0 * TT], rb1 = epB[1 * TT], rb2 = epB[2 * TT], rb3 = epB[3 * TT];
        int DA = 0, DB = 0;
        HBAR(bar);

#pragma unroll 4
        for (int t = 0; t < LL; ++t) {
            float na = (t + 4 < LL) ? epA[(t + 4) * TT] : 0.0f;
            float nb = (t + 4 < LL) ? epB[(t + 4) * TT] : 0.0f;

            const float EA = __expf(ra0);
            const float EB = __expf(rb0);

            const int bu = t & 1;
            const float* qa = q_sh[2 * h + 0][bu];
            const float* qb = q_sh[2 * h + 1][bu];

            // Power-of-two renorm from q[0] exponent field (ALU-only, off-chain).
            const unsigned ea = __float_as_uint(qa[0]) & 0x7f800000u;
            const unsigned eb = __float_as_uint(qb[0]) & 0x7f800000u;
            const float rA = ea ? __uint_as_float(0x7f000000u - ea) : 1.0f;
            const float rB = eb ? __uint_as_float(0x7f000000u - eb) : 1.0f;
            DA += ea ? ((int)(ea >> 23) - 127) : 0;
            DB += eb ? ((int)(eb >> 23) - 127) : 0;
            const float mA = EA * rA;
            const float mB = EB * rB;

            float sa, sb;
            dot64x2(qa, qb, P2, sa, sb);
            q_sh[2 * h + 0][bu ^ 1][l] = sa * mA;
            q_sh[2 * h + 1][bu ^ 1][l] = sb * mB;
            HBAR(bar);

            ra0 = ra1; ra1 = ra2; ra2 = ra3; ra3 = na;
            rb0 = rb1; rb1 = rb2; rb2 = rb3; rb3 = nb;
        }

        const float qfA = q_sh[2 * h + 0][0][l];
        const float qfB = q_sh[2 * h + 1][0][l];
        aA = (qfA > 0.0f) ? __logf(qfA) : -1.0e30f;
        aB = (qfB > 0.0f) ? __logf(qfB) : -1.0e30f;
        CA = (float)DA * 0.6931471805599453f;
        CB = (float)DB * 0.6931471805599453f;
    } else {
        // ===== general masked path (log space; rare, correctness-first) =======
        for (int g = 0; g < 2; ++g) {
            const int seq = sA + g;
            const float* ep = inputs + (size_t)seq * LL * TT + l;
            float a = (l == START_TAG) ? 0.0f : -10000.0f;
            float C = 0.0f;
            for (int t = 0; t < LL; ++t) {
                q_sh[2 * h + g][0][l] = __expf(a);
                HBAR(bar);
                const float mf = (float)mask[seq * LL + t];
                float s;
                if (mf != 0.0f) {
                    s = dot64(q_sh[2 * h + g][0], P2);
                } else {
                    float acc = 0.f;
#pragma unroll
                    for (int j = 0; j < TT; ++j) acc += q_sh[2 * h + g][0][j];
                    s = acc;
                }
                float d = fmaf(mf, ep[t * TT], __logf(s));
                d = fmaxf(d, -1.0e30f);
                if (l == 0) dsl[h] = d;
                HBAR(bar);
                const float d0 = dsl[h];
                a = d - d0;
                C += d0;
            }
            if (g == 0) { aA = a; CA = C; } else { aB = a; CB = C; }
        }
    }

    // ================= per-sequence finale (half-local reductions) ============
#pragma unroll
    for (int g = 0; g < 2; ++g) {
        const int seq = sA + g;
        const float a = g ? aB : aA;
        const float C = g ? CB : CA;

        const float term = fmaxf(a + trans[STOP_TAG * TT + l], -1.0e30f);
        red2[h][l] = term;
        HBAR(bar);
#pragma unroll
        for (int off = TT / 2; off > 0; off >>= 1) {
            if (l < off) red2[h][l] = fmaxf(red2[h][l], red2[h][l + off]);
            HBAR(bar);
        }
        const float mx = red2[h][0];
        HBAR(bar);
        red2[h][l] = __expf(term - mx);
        HBAR(bar);
#pragma unroll
        for (int off = TT / 2; off > 0; off >>= 1) {
            if (l < off) red2[h][l] += red2[h][l + off];
            HBAR(bar);
        }
        const float logden = C + mx + __logf(red2[h][0]);
        HBAR(bar);

        // numerator path score (gold tags)
        float sc = 0.f;
        const float* in_b = inputs + (size_t)seq * LL * TT;
        const int*   tg   = tags + seq * LL;
        const int*   mk   = mask + seq * LL;
        for (int t = l; t < LL - 1; t += 64) {
            const int pt = tg[t];
            const int nt = tg[t + 1];
            sc += trans[nt * TT + pt] * (float)mk[t + 1]
                + in_b[t * TT + pt] * (float)mk[t];
        }
        red2[h][l] = sc;
        HBAR(bar);
#pragma unroll
        for (int off = TT / 2; off > 0; off >>= 1) {
            if (l < off) red2[h][l] += red2[h][l + off];
            HBAR(bar);
        }
        if (l == 0) {
            const int t0  = tg[0];
            const int tl_ = tg[LL - 1];
            float score = red2[h][0]
                        + trans[t0 * TT + START_TAG]
                        + trans[STOP_TAG * TT + tl_]
                        + in_b[(LL - 1) * TT + tl_] * (float)mk[LL - 1];
            g_partials[seq] = score - logden;
        }
        HBAR(bar);
    }

    // ---- deterministic fixed-order final reduction in the last block ----
    __syncthreads();
    if (tid == 0) {
        __threadfence();
        int old = atomicAdd(&g_count, 1);
        islast = (old == (int)gridDim.x - 1);
    }
    __syncthreads();
    if (islast) {
        __threadfence();
        float s = 0.f;
#pragma unroll
        for (int k = 0; k < 4; ++k)            // 128 threads x 4 = 512, fixed order
            s += g_partials[tid * 4 + k];
        float* rf = &red2[0][0];               // 128 contiguous floats
        rf[tid] = s;
        __syncthreads();
#pragma unroll
        for (int off = 64; off > 0; off >>= 1) {
            if (tid < off) rf[tid] += rf[tid + off];
            __syncthreads();
        }
        if (tid == 0) {
            out[0] = rf[0];
            g_count = 0;
        }
    }
}

extern "C" void kernel_launch(void* const* d_in, const int* in_sizes, int n_in,
                              void* d_out, int out_size)
{
    const float* inputs = (const float*)d_in[0];
    const int*   tags   = (const int*)d_in[1];
    const int*   mask   = (const int*)d_in[2];
    const float* trans  = (const float*)d_in[3];

    crf_fused_kernel<<<NBLK, 128>>>(inputs, tags, mask, trans, (float*)d_out);
}